// round 9
// baseline (speedup 1.0000x reference)
#include <cuda_runtime.h>
#include <cuda_bf16.h>
#include <cstdint>

// NVAR feature expansion:
//   X: (8, 4, 4096) f32  ->  out: (8, 4, 3996, 231) f32
//   features per (b,r,t): [1, tap_0..tap_9, 220 degree-3 monomials (i<=j<=k)]
//   tap_k = X[b, r, t + 2k - 18], t = tout + 100  (always in-bounds)

#define KTAPS   10
#define NMON    220
#define NF      231                 // 1 + KTAPS + NMON
#define NT_IN   4096
#define TRANS   100
#define NT_OUT  (NT_IN - TRANS)     // 3996
#define PADL    18                  // (KTAPS-1)*SKIP
#define TILE_T  32
#define NTHREADS 128                // 4 warps -> up to 7 resident CTAs/SM

// Per-group feature ranges over [0, 231): groups 0..6 get 29, group 7 gets 28.
template <int G>
__device__ __forceinline__ void do_feats(const float (&x)[KTAPS], float* __restrict__ srow) {
    constexpr int LO = G * 29;
    constexpr int HI = (G == 7) ? NF : LO + 29;

    if (LO == 0) srow[0] = 1.0f;

    #pragma unroll
    for (int t = 0; t < KTAPS; ++t)
        if (t + 1 >= LO && t + 1 < HI) srow[t + 1] = x[t];

    // monomials in lexicographic (a<=b<=c) order; product ((xa*xb)*xc) == jnp.prod order
    int m = 0;
    #pragma unroll
    for (int a = 0; a < KTAPS; ++a) {
        #pragma unroll
        for (int b = a; b < KTAPS; ++b) {
            float xab = x[a] * x[b];            // DCE'd when no store lands in [LO,HI)
            #pragma unroll
            for (int c = b; c < KTAPS; ++c) {
                int f = 1 + KTAPS + m;
                if (f >= LO && f < HI) srow[f] = xab * x[c];
                ++m;
            }
        }
    }
}

__device__ __forceinline__ uint32_t smem_u32(const void* p) {
    uint32_t a;
    asm("{ .reg .u64 t; cvta.to.shared.u64 t, %1; cvt.u32.u64 %0, t; }" : "=r"(a) : "l"(p));
    return a;
}

__global__ __launch_bounds__(NTHREADS)
void nvar_kernel(const float* __restrict__ X, float* __restrict__ out) {
    __shared__ alignas(16) float s_out[TILE_T * NF];    // 29568 B, layout == global rows

    const int tid   = threadIdx.x;
    const int tl    = tid & (TILE_T - 1);       // time-step within tile (0..31)
    const int g     = tid >> 5;                 // warp id = feature-group base (0..3)
    const int br    = blockIdx.y;               // b*4 + r, 0..31
    const int t0    = blockIdx.x * TILE_T;
    const int valid = min(TILE_T, NT_OUT - t0); // 32, or 28 on the last tile

    if (tl < valid) {
        const float* Xtap = X + (size_t)br * NT_IN + (TRANS - PADL) + t0 + tl;
        float x[KTAPS];
        #pragma unroll
        for (int t = 0; t < KTAPS; ++t)
            x[t] = __ldg(Xtap + 2 * t);                  // L1-hot, coalesced per warp

        float* srow = s_out + tl * NF;          // stride 231 words -> 32 distinct banks
        // each warp handles two feature groups: g and g+4 (warp-uniform, no divergence)
        switch (g) {
            case 0: do_feats<0>(x, srow); do_feats<4>(x, srow); break;
            case 1: do_feats<1>(x, srow); do_feats<5>(x, srow); break;
            case 2: do_feats<2>(x, srow); do_feats<6>(x, srow); break;
            default: do_feats<3>(x, srow); do_feats<7>(x, srow); break;
        }
    }
    __syncthreads();

    // single bulk async copy shared -> global: valid*924 B, 16B-aligned both sides
    if (tid == 0) {
        float* gdst = out + ((size_t)br * NT_OUT + t0) * NF;
        uint32_t src    = smem_u32(s_out);
        uint32_t nbytes = (uint32_t)valid * (NF * 4);
        asm volatile("fence.proxy.async.shared::cta;" ::: "memory");
        asm volatile("cp.async.bulk.global.shared::cta.bulk_group [%0], [%1], %2;"
                     :: "l"(gdst), "r"(src), "r"(nbytes) : "memory");
        asm volatile("cp.async.bulk.commit_group;" ::: "memory");
        asm volatile("cp.async.bulk.wait_group 0;" ::: "memory");
    }
    // other warps exit immediately; CTA slot frees when thread 0's wait completes.
    // Cross-CTA overlap (7 CTAs/SM) hides the drain latency.
}

extern "C" void kernel_launch(void* const* d_in, const int* in_sizes, int n_in,
                              void* d_out, int out_size) {
    const float* X   = (const float*)d_in[0];
    float*       out = (float*)d_out;

    const int br_total = in_sizes[0] / NT_IN;                 // 32
    dim3 grid((NT_OUT + TILE_T - 1) / TILE_T, br_total);      // 125 x 32 = 4000 blocks
    nvar_kernel<<<grid, NTHREADS>>>(X, out);
}

// round 10
// speedup vs baseline: 1.4031x; 1.4031x over previous
#include <cuda_runtime.h>
#include <cuda_bf16.h>
#include <cstdint>

// NVAR feature expansion:
//   X: (8, 4, 4096) f32  ->  out: (8, 4, 3996, 231) f32
//   features per (b,r,t): [1, tap_0..tap_9, 220 degree-3 monomials (i<=j<=k)]
//   tap_k = X[b, r, t + 2k - 18], t = tout + 100  (always in-bounds)

#define KTAPS   10
#define NMON    220
#define NF      231                 // 1 + KTAPS + NMON
#define NT_IN   4096
#define TRANS   100
#define NT_OUT  (NT_IN - TRANS)     // 3996
#define PADL    18                  // (KTAPS-1)*SKIP
#define TILE_T  32
#define NTHREADS 256

// Per-group feature ranges over [0, 231): groups 0..6 get 29, group 7 gets 28.
template <int G>
__device__ __forceinline__ void do_feats(const float (&x)[KTAPS], float* __restrict__ srow) {
    constexpr int LO = G * 29;
    constexpr int HI = (G == 7) ? NF : LO + 29;

    if (LO == 0) srow[0] = 1.0f;

    #pragma unroll
    for (int t = 0; t < KTAPS; ++t)
        if (t + 1 >= LO && t + 1 < HI) srow[t + 1] = x[t];

    // monomials in lexicographic (a<=b<=c) order; product ((xa*xb)*xc) == jnp.prod order
    int m = 0;
    #pragma unroll
    for (int a = 0; a < KTAPS; ++a) {
        #pragma unroll
        for (int b = a; b < KTAPS; ++b) {
            float xab = x[a] * x[b];            // DCE'd when no store lands in [LO,HI)
            #pragma unroll
            for (int c = b; c < KTAPS; ++c) {
                int f = 1 + KTAPS + m;
                if (f >= LO && f < HI) srow[f] = xab * x[c];
                ++m;
            }
        }
    }
}

__global__ __launch_bounds__(NTHREADS)
void nvar_kernel(const float* __restrict__ X, float* __restrict__ out) {
    __shared__ alignas(16) float s_out[TILE_T * NF];    // 29568 B, layout == global rows

    const int tid   = threadIdx.x;
    const int tl    = tid & (TILE_T - 1);       // time-step within tile (0..31)
    const int g     = tid >> 5;                 // warp id = feature group (0..7)
    const int br    = blockIdx.y;               // b*4 + r, 0..31
    const int t0    = blockIdx.x * TILE_T;
    const int valid = min(TILE_T, NT_OUT - t0); // 32, or 28 on the last tile

    if (tl < valid) {
        const float* Xtap = X + (size_t)br * NT_IN + (TRANS - PADL) + t0 + tl;
        float x[KTAPS];
        #pragma unroll
        for (int t = 0; t < KTAPS; ++t)
            x[t] = __ldg(Xtap + 2 * t);                  // L1-hot, coalesced per warp

        float* srow = s_out + tl * NF;          // stride 231 words -> 32 distinct banks
        switch (g) {                            // warp-uniform, no divergence
            case 0: do_feats<0>(x, srow); break;
            case 1: do_feats<1>(x, srow); break;
            case 2: do_feats<2>(x, srow); break;
            case 3: do_feats<3>(x, srow); break;
            case 4: do_feats<4>(x, srow); break;
            case 5: do_feats<5>(x, srow); break;
            case 6: do_feats<6>(x, srow); break;
            default: do_feats<7>(x, srow); break;
        }
    }
    __syncthreads();

    // Drain: the whole tile is a flat run of valid*NF floats whose global base
    // (br*3996 + t0)*231*4 B is 16B-aligned (3996%4==0, t0%4==0, valid*NF%4==0).
    // Fire-and-forget STG.128: no TMA wait holding the CTA slot.
    {
        const float4* s4 = reinterpret_cast<const float4*>(s_out);
        float4* g4 = reinterpret_cast<float4*>(out + ((size_t)br * NT_OUT + t0) * NF);
        const int n4 = (valid * NF) >> 2;       // 1848 or 1617
        #pragma unroll 4
        for (int i = tid; i < n4; i += NTHREADS)
            __stcs(g4 + i, s4[i]);              // streaming store, coalesced 128B/warp
    }
}

extern "C" void kernel_launch(void* const* d_in, const int* in_sizes, int n_in,
                              void* d_out, int out_size) {
    const float* X   = (const float*)d_in[0];
    float*       out = (float*)d_out;

    const int br_total = in_sizes[0] / NT_IN;                 // 32
    dim3 grid((NT_OUT + TILE_T - 1) / TILE_T, br_total);      // 125 x 32 = 4000 blocks
    nvar_kernel<<<grid, NTHREADS>>>(X, out);
}